// round 1
// baseline (speedup 1.0000x reference)
#include <cuda_runtime.h>

#define HDIM 768
#define TT 4
#define TSTART 2
#define TSTOP 3
#define NB 64
#define NS1 513
#define NS 512

// Output layout (float32), tuple order:
// isqa_pred (64), crf_pred (64*512), isqa_loss (1), crf_loss (1), tags (64*512), IsQA (64)
#define OFF_ISQA_PRED 0
#define OFF_CRF_PRED  64
#define OFF_ISQA_LOSS (64 + NB*NS)          // 32832
#define OFF_CRF_LOSS  (OFF_ISQA_LOSS + 1)   // 32833
#define OFF_TAGS      (OFF_CRF_LOSS + 1)    // 32834
#define OFF_ISQA      (OFF_TAGS + NB*NS)    // 65602

__device__ __align__(16) float g_feats[NB * NS * TT];  // 512 KB scratch
__device__ float g_isqa_loss[NB];
__device__ float g_zg[NB];

// ---------------------------------------------------------------------------
// Kernel A: feats[b][s][t] = emb[b][s+1] . crf_W[t] + crf_b[t]
//           plus isqa logits for the CLS row (s1 == 0), tags copy, IsQA copy.
// One warp per (b, s1) row. Weights staged in shared memory.
// ---------------------------------------------------------------------------
__global__ __launch_bounds__(256)
void feats_kernel(const float* __restrict__ emb,
                  const int* __restrict__ asl,
                  const int* __restrict__ isqa,
                  const float* __restrict__ fc2W,
                  const float* __restrict__ fc2b,
                  const float* __restrict__ crfW,
                  const float* __restrict__ crfb,
                  float* __restrict__ out)
{
    // sW rows 0..3 = crf_W[0..3], rows 4..5 = fc2_W[0..1]; each row HDIM floats
    __shared__ float4 sW[6 * (HDIM / 4)];
    const int ROWQ = HDIM / 4;  // 192
    for (int i = threadIdx.x; i < 6 * ROWQ; i += blockDim.x) {
        int row = i / ROWQ;
        int col = i % ROWQ;
        const float* p = (row < 4) ? (crfW + row * HDIM) : (fc2W + (row - 4) * HDIM);
        sW[i] = reinterpret_cast<const float4*>(p)[col];
    }
    __syncthreads();

    int warp = threadIdx.x >> 5;
    int lane = threadIdx.x & 31;
    int r = blockIdx.x * (blockDim.x >> 5) + warp;
    if (r >= NB * NS1) return;
    int b = r / NS1;
    int s1 = r % NS1;
    const float4* row = reinterpret_cast<const float4*>(emb + (size_t)r * HDIM);

    if (s1 > 0) {
        float a0 = 0.f, a1 = 0.f, a2 = 0.f, a3 = 0.f;
        #pragma unroll
        for (int j = 0; j < 6; j++) {
            int c = lane + 32 * j;
            float4 v = row[c];
            float4 w0 = sW[0 * ROWQ + c];
            float4 w1 = sW[1 * ROWQ + c];
            float4 w2 = sW[2 * ROWQ + c];
            float4 w3 = sW[3 * ROWQ + c];
            a0 += v.x * w0.x + v.y * w0.y + v.z * w0.z + v.w * w0.w;
            a1 += v.x * w1.x + v.y * w1.y + v.z * w1.z + v.w * w1.w;
            a2 += v.x * w2.x + v.y * w2.y + v.z * w2.z + v.w * w2.w;
            a3 += v.x * w3.x + v.y * w3.y + v.z * w3.z + v.w * w3.w;
        }
        #pragma unroll
        for (int o = 16; o; o >>= 1) {
            a0 += __shfl_xor_sync(0xffffffffu, a0, o);
            a1 += __shfl_xor_sync(0xffffffffu, a1, o);
            a2 += __shfl_xor_sync(0xffffffffu, a2, o);
            a3 += __shfl_xor_sync(0xffffffffu, a3, o);
        }
        if (lane == 0) {
            float4 f;
            f.x = a0 + crfb[0];
            f.y = a1 + crfb[1];
            f.z = a2 + crfb[2];
            f.w = a3 + crfb[3];
            reinterpret_cast<float4*>(g_feats)[b * NS + (s1 - 1)] = f;
        }
        if (lane == 1) {
            out[OFF_TAGS + b * NS + (s1 - 1)] = (float)asl[b * NS1 + s1];
        }
    } else {
        float a0 = 0.f, a1 = 0.f;
        #pragma unroll
        for (int j = 0; j < 6; j++) {
            int c = lane + 32 * j;
            float4 v = row[c];
            float4 w0 = sW[4 * ROWQ + c];
            float4 w1 = sW[5 * ROWQ + c];
            a0 += v.x * w0.x + v.y * w0.y + v.z * w0.z + v.w * w0.w;
            a1 += v.x * w1.x + v.y * w1.y + v.z * w1.z + v.w * w1.w;
        }
        #pragma unroll
        for (int o = 16; o; o >>= 1) {
            a0 += __shfl_xor_sync(0xffffffffu, a0, o);
            a1 += __shfl_xor_sync(0xffffffffu, a1, o);
        }
        if (lane == 0) {
            float l0 = a0 + fc2b[0];
            float l1 = a1 + fc2b[1];
            int pred = (l1 > l0) ? 1 : 0;  // first-max on ties
            float m = fmaxf(l0, l1);
            float lse = m + __logf(__expf(l0 - m) + __expf(l1 - m));
            int q = isqa[b];
            out[OFF_ISQA_PRED + b] = (float)pred;
            out[OFF_ISQA + b] = (float)q;
            g_isqa_loss[b] = lse - (q ? l1 : l0);
        }
    }
}

// ---------------------------------------------------------------------------
// Kernel B: per-batch CRF forward (log-partition), Viterbi fwd + backtrack,
//           gold score. One warp per batch.
// ---------------------------------------------------------------------------
__global__ __launch_bounds__(32)
void crf_kernel(const int* __restrict__ asl,
                const float* __restrict__ trans,
                float* __restrict__ out)
{
    __shared__ __align__(16) float sf[NS * TT];   // 8 KB feats for this batch
    __shared__ unsigned char sbp[NS];             // packed backpointers
    __shared__ float str[16];

    int b = blockIdx.x;
    int lane = threadIdx.x;

    const float4* gf = reinterpret_cast<const float4*>(g_feats + (size_t)b * NS * TT);
    float4* sf4 = reinterpret_cast<float4*>(sf);
    for (int i = lane; i < NS; i += 32) sf4[i] = gf[i];
    if (lane < 16) str[lane] = trans[lane];
    __syncwarp();

    // --- gold score (all lanes) ---
    const int* tagp = asl + b * NS1 + 1;  // tags[s] = asl[b*513 + 1 + s]
    float partial = 0.f;
    for (int s = lane; s < NS; s += 32) {
        int t = tagp[s];
        partial += sf[s * 4 + t];
        if (s < NS - 1) partial += str[t * 4 + tagp[s + 1]];
    }
    #pragma unroll
    for (int o = 16; o; o >>= 1) partial += __shfl_xor_sync(0xffffffffu, partial, o);

    if (lane == 0) {
        float gold = partial + str[TSTART * 4 + tagp[0]] + str[tagp[NS - 1] * 4 + TSTOP];

        float tr[4][4];
        #pragma unroll
        for (int i = 0; i < 4; i++)
            #pragma unroll
            for (int j = 0; j < 4; j++) tr[i][j] = str[i * 4 + j];

        float a[4], d[4];
        {
            float4 f0 = sf4[0];
            float fv[4] = {f0.x, f0.y, f0.z, f0.w};
            #pragma unroll
            for (int j = 0; j < 4; j++) {
                a[j] = fv[j] + tr[TSTART][j];
                d[j] = a[j];
            }
        }

        for (int s = 1; s < NS; s++) {
            float4 f = sf4[s];
            float fv[4] = {f.x, f.y, f.z, f.w};
            float na[4], nd[4];
            unsigned bp = 0;
            #pragma unroll
            for (int j = 0; j < 4; j++) {
                // logsumexp chain
                float v0 = a[0] + tr[0][j];
                float v1 = a[1] + tr[1][j];
                float v2 = a[2] + tr[2][j];
                float v3 = a[3] + tr[3][j];
                float m = fmaxf(fmaxf(v0, v1), fmaxf(v2, v3));
                float ssum = __expf(v0 - m) + __expf(v1 - m) + __expf(v2 - m) + __expf(v3 - m);
                na[j] = m + __logf(ssum) + fv[j];
                // viterbi chain (first-max on ties)
                float w0 = d[0] + tr[0][j];
                float w1 = d[1] + tr[1][j];
                float w2 = d[2] + tr[2][j];
                float w3 = d[3] + tr[3][j];
                float bbest = w0; int bi = 0;
                if (w1 > bbest) { bbest = w1; bi = 1; }
                if (w2 > bbest) { bbest = w2; bi = 2; }
                if (w3 > bbest) { bbest = w3; bi = 3; }
                nd[j] = bbest + fv[j];
                bp |= (unsigned)bi << (2 * j);
            }
            sbp[s] = (unsigned char)bp;
            #pragma unroll
            for (int j = 0; j < 4; j++) { a[j] = na[j]; d[j] = nd[j]; }
        }

        // Z = logsumexp(a + trans[:, STOP])
        float v0 = a[0] + tr[0][TSTOP];
        float v1 = a[1] + tr[1][TSTOP];
        float v2 = a[2] + tr[2][TSTOP];
        float v3 = a[3] + tr[3][TSTOP];
        float m = fmaxf(fmaxf(v0, v1), fmaxf(v2, v3));
        float Z = m + __logf(__expf(v0 - m) + __expf(v1 - m) + __expf(v2 - m) + __expf(v3 - m));
        g_zg[b] = Z - gold;

        // last tag = argmax(d + trans[:, STOP]), first-max on ties
        float w0 = d[0] + tr[0][TSTOP];
        float w1 = d[1] + tr[1][TSTOP];
        float w2 = d[2] + tr[2][TSTOP];
        float w3 = d[3] + tr[3][TSTOP];
        float bbest = w0; int lt = 0;
        if (w1 > bbest) { bbest = w1; lt = 1; }
        if (w2 > bbest) { bbest = w2; lt = 2; }
        if (w3 > bbest) { bbest = w3; lt = 3; }

        float* outp = out + OFF_CRF_PRED + b * NS;
        int cur = lt;
        outp[NS - 1] = (float)cur;
        for (int s = NS - 1; s >= 1; s--) {
            cur = (sbp[s] >> (2 * cur)) & 3;
            outp[s - 1] = (float)cur;
        }
    }
}

// ---------------------------------------------------------------------------
// Kernel C: final loss reductions
// ---------------------------------------------------------------------------
__global__ __launch_bounds__(32)
void loss_kernel(float* __restrict__ out)
{
    int lane = threadIdx.x;
    float v1 = g_isqa_loss[lane] + g_isqa_loss[lane + 32];
    float v2 = g_zg[lane] + g_zg[lane + 32];
    #pragma unroll
    for (int o = 16; o; o >>= 1) {
        v1 += __shfl_xor_sync(0xffffffffu, v1, o);
        v2 += __shfl_xor_sync(0xffffffffu, v2, o);
    }
    if (lane == 0) {
        out[OFF_ISQA_LOSS] = v1 * (1.0f / NB);
        out[OFF_CRF_LOSS]  = v2 * (1.0f / NB);
    }
}

extern "C" void kernel_launch(void* const* d_in, const int* in_sizes, int n_in,
                              void* d_out, int out_size)
{
    const float* emb   = (const float*)d_in[0];
    const int*   asl   = (const int*)d_in[1];
    const int*   isqa  = (const int*)d_in[2];
    const float* fc2W  = (const float*)d_in[3];
    const float* fc2b  = (const float*)d_in[4];
    const float* crfW  = (const float*)d_in[5];
    const float* crfb  = (const float*)d_in[6];
    const float* trans = (const float*)d_in[7];
    float* out = (float*)d_out;

    int rows = NB * NS1;                 // 32832
    int blocks = (rows + 7) / 8;         // 8 warps per 256-thread block
    feats_kernel<<<blocks, 256>>>(emb, asl, isqa, fc2W, fc2b, crfW, crfb, out);
    crf_kernel<<<NB, 32>>>(asl, trans, out);
    loss_kernel<<<1, 32>>>(out);
}

// round 2
// speedup vs baseline: 2.7145x; 2.7145x over previous
#include <cuda_runtime.h>

#define HDIM 768
#define TT 4
#define TSTART 2
#define TSTOP 3
#define NB 64
#define NS1 513
#define NS 512

// Output layout (float32), tuple order:
// isqa_pred (64), crf_pred (64*512), isqa_loss (1), crf_loss (1), tags (64*512), IsQA (64)
#define OFF_ISQA_PRED 0
#define OFF_CRF_PRED  64
#define OFF_ISQA_LOSS (64 + NB*NS)          // 32832
#define OFF_CRF_LOSS  (OFF_ISQA_LOSS + 1)   // 32833
#define OFF_TAGS      (OFF_CRF_LOSS + 1)    // 32834
#define OFF_ISQA      (OFF_TAGS + NB*NS)    // 65602

__device__ __align__(16) float g_feats[NB * NS * TT];  // 512 KB scratch
__device__ float g_isqa_loss[NB];
__device__ float g_zg[NB];

#define ROWQ (HDIM / 4)   // 192

// ---------------------------------------------------------------------------
// Kernel A: feats GEMV. 4 rows per warp (amortize smem weight reads).
// ---------------------------------------------------------------------------
__global__ __launch_bounds__(256)
void feats_kernel(const float* __restrict__ emb,
                  const int* __restrict__ asl,
                  const int* __restrict__ isqa,
                  const float* __restrict__ fc2W,
                  const float* __restrict__ fc2b,
                  const float* __restrict__ crfW,
                  const float* __restrict__ crfb,
                  float* __restrict__ out)
{
    __shared__ float4 sW[6 * ROWQ];  // rows 0..3 crf_W, rows 4..5 fc2_W
    for (int i = threadIdx.x; i < 6 * ROWQ; i += blockDim.x) {
        int row = i / ROWQ;
        int col = i % ROWQ;
        const float* p = (row < 4) ? (crfW + row * HDIM) : (fc2W + (row - 4) * HDIM);
        sW[i] = reinterpret_cast<const float4*>(p)[col];
    }
    __syncthreads();

    int warp = threadIdx.x >> 5;
    int lane = threadIdx.x & 31;
    int r0 = (blockIdx.x * 8 + warp) * 4;
    if (r0 >= NB * NS1) return;

    bool hasCLS = false;
    #pragma unroll
    for (int k = 0; k < 4; k++) if ((r0 + k) % NS1 == 0) hasCLS = true;

    if (!hasCLS) {
        // ---- fast path: 4 non-CLS rows ----
        const float4* rp0 = reinterpret_cast<const float4*>(emb + (size_t)(r0 + 0) * HDIM);
        const float4* rp1 = reinterpret_cast<const float4*>(emb + (size_t)(r0 + 1) * HDIM);
        const float4* rp2 = reinterpret_cast<const float4*>(emb + (size_t)(r0 + 2) * HDIM);
        const float4* rp3 = reinterpret_cast<const float4*>(emb + (size_t)(r0 + 3) * HDIM);

        float a[4][4];
        #pragma unroll
        for (int k = 0; k < 4; k++)
            #pragma unroll
            for (int t = 0; t < 4; t++) a[k][t] = 0.f;

        #pragma unroll
        for (int j = 0; j < 6; j++) {
            int c = lane + 32 * j;
            float4 w0 = sW[0 * ROWQ + c];
            float4 w1 = sW[1 * ROWQ + c];
            float4 w2 = sW[2 * ROWQ + c];
            float4 w3 = sW[3 * ROWQ + c];
            float4 v0 = rp0[c];
            float4 v1 = rp1[c];
            float4 v2 = rp2[c];
            float4 v3 = rp3[c];
            a[0][0] += v0.x*w0.x + v0.y*w0.y + v0.z*w0.z + v0.w*w0.w;
            a[0][1] += v0.x*w1.x + v0.y*w1.y + v0.z*w1.z + v0.w*w1.w;
            a[0][2] += v0.x*w2.x + v0.y*w2.y + v0.z*w2.z + v0.w*w2.w;
            a[0][3] += v0.x*w3.x + v0.y*w3.y + v0.z*w3.z + v0.w*w3.w;
            a[1][0] += v1.x*w0.x + v1.y*w0.y + v1.z*w0.z + v1.w*w0.w;
            a[1][1] += v1.x*w1.x + v1.y*w1.y + v1.z*w1.z + v1.w*w1.w;
            a[1][2] += v1.x*w2.x + v1.y*w2.y + v1.z*w2.z + v1.w*w2.w;
            a[1][3] += v1.x*w3.x + v1.y*w3.y + v1.z*w3.z + v1.w*w3.w;
            a[2][0] += v2.x*w0.x + v2.y*w0.y + v2.z*w0.z + v2.w*w0.w;
            a[2][1] += v2.x*w1.x + v2.y*w1.y + v2.z*w1.z + v2.w*w1.w;
            a[2][2] += v2.x*w2.x + v2.y*w2.y + v2.z*w2.z + v2.w*w2.w;
            a[2][3] += v2.x*w3.x + v2.y*w3.y + v2.z*w3.z + v2.w*w3.w;
            a[3][0] += v3.x*w0.x + v3.y*w0.y + v3.z*w0.z + v3.w*w0.w;
            a[3][1] += v3.x*w1.x + v3.y*w1.y + v3.z*w1.z + v3.w*w1.w;
            a[3][2] += v3.x*w2.x + v3.y*w2.y + v3.z*w2.z + v3.w*w2.w;
            a[3][3] += v3.x*w3.x + v3.y*w3.y + v3.z*w3.z + v3.w*w3.w;
        }
        #pragma unroll
        for (int o = 16; o; o >>= 1)
            #pragma unroll
            for (int k = 0; k < 4; k++)
                #pragma unroll
                for (int t = 0; t < 4; t++)
                    a[k][t] += __shfl_xor_sync(0xffffffffu, a[k][t], o);

        if (lane == 0) {
            float b0 = crfb[0], b1 = crfb[1], b2 = crfb[2], b3 = crfb[3];
            #pragma unroll
            for (int k = 0; k < 4; k++) {
                int r = r0 + k;
                int b = r / NS1;
                int s1 = r % NS1;
                float4 f;
                f.x = a[k][0] + b0; f.y = a[k][1] + b1;
                f.z = a[k][2] + b2; f.w = a[k][3] + b3;
                reinterpret_cast<float4*>(g_feats)[b * NS + (s1 - 1)] = f;
            }
        }
        if (lane == 1) {
            #pragma unroll
            for (int k = 0; k < 4; k++) {
                int r = r0 + k;
                int b = r / NS1;
                int s1 = r % NS1;
                out[OFF_TAGS + b * NS + (s1 - 1)] = (float)asl[r];
            }
        }
    } else {
        // ---- slow path: per-row (handles CLS rows) ----
        for (int k = 0; k < 4; k++) {
            int r = r0 + k;
            int b = r / NS1;
            int s1 = r % NS1;
            const float4* row = reinterpret_cast<const float4*>(emb + (size_t)r * HDIM);
            if (s1 > 0) {
                float a0 = 0.f, a1 = 0.f, a2 = 0.f, a3 = 0.f;
                #pragma unroll
                for (int j = 0; j < 6; j++) {
                    int c = lane + 32 * j;
                    float4 v = row[c];
                    float4 w0 = sW[0 * ROWQ + c];
                    float4 w1 = sW[1 * ROWQ + c];
                    float4 w2 = sW[2 * ROWQ + c];
                    float4 w3 = sW[3 * ROWQ + c];
                    a0 += v.x*w0.x + v.y*w0.y + v.z*w0.z + v.w*w0.w;
                    a1 += v.x*w1.x + v.y*w1.y + v.z*w1.z + v.w*w1.w;
                    a2 += v.x*w2.x + v.y*w2.y + v.z*w2.z + v.w*w2.w;
                    a3 += v.x*w3.x + v.y*w3.y + v.z*w3.z + v.w*w3.w;
                }
                #pragma unroll
                for (int o = 16; o; o >>= 1) {
                    a0 += __shfl_xor_sync(0xffffffffu, a0, o);
                    a1 += __shfl_xor_sync(0xffffffffu, a1, o);
                    a2 += __shfl_xor_sync(0xffffffffu, a2, o);
                    a3 += __shfl_xor_sync(0xffffffffu, a3, o);
                }
                if (lane == 0) {
                    float4 f;
                    f.x = a0 + crfb[0]; f.y = a1 + crfb[1];
                    f.z = a2 + crfb[2]; f.w = a3 + crfb[3];
                    reinterpret_cast<float4*>(g_feats)[b * NS + (s1 - 1)] = f;
                }
                if (lane == 1) {
                    out[OFF_TAGS + b * NS + (s1 - 1)] = (float)asl[r];
                }
            } else {
                float a0 = 0.f, a1 = 0.f;
                #pragma unroll
                for (int j = 0; j < 6; j++) {
                    int c = lane + 32 * j;
                    float4 v = row[c];
                    float4 w0 = sW[4 * ROWQ + c];
                    float4 w1 = sW[5 * ROWQ + c];
                    a0 += v.x*w0.x + v.y*w0.y + v.z*w0.z + v.w*w0.w;
                    a1 += v.x*w1.x + v.y*w1.y + v.z*w1.z + v.w*w1.w;
                }
                #pragma unroll
                for (int o = 16; o; o >>= 1) {
                    a0 += __shfl_xor_sync(0xffffffffu, a0, o);
                    a1 += __shfl_xor_sync(0xffffffffu, a1, o);
                }
                if (lane == 0) {
                    float l0 = a0 + fc2b[0];
                    float l1 = a1 + fc2b[1];
                    int pred = (l1 > l0) ? 1 : 0;
                    float m = fmaxf(l0, l1);
                    float lse = m + __logf(__expf(l0 - m) + __expf(l1 - m));
                    int q = isqa[b];
                    out[OFF_ISQA_PRED + b] = (float)pred;
                    out[OFF_ISQA + b] = (float)q;
                    g_isqa_loss[b] = lse - (q ? l1 : l0);
                }
            }
        }
    }
}

// tag-map composition: (a ∘ b)(t) = a[b[t]], maps stored as 4 bytes (values 0..3)
__device__ __forceinline__ unsigned cmap(unsigned a, unsigned b) {
    unsigned sel = (b & 3u) | ((b >> 4) & 0x30u) | ((b >> 8) & 0x300u) | ((b >> 12) & 0x3000u);
    return __byte_perm(a, 0, sel);
}

__device__ __forceinline__ void rescale16(float C[4][4], float& logacc) {
    float mx = C[0][0];
    #pragma unroll
    for (int i = 0; i < 4; i++)
        #pragma unroll
        for (int j = 0; j < 4; j++) mx = fmaxf(mx, C[i][j]);
    int e = (__float_as_int(mx) >> 23) & 255;
    float inv = __int_as_float((254 - e) << 23);   // exact 2^(127-e)
    logacc += (float)(e - 127) * 0.6931471805599453f;
    #pragma unroll
    for (int i = 0; i < 4; i++)
        #pragma unroll
        for (int j = 0; j < 4; j++) C[i][j] *= inv;
}

// ---------------------------------------------------------------------------
// Kernel B: per-batch CRF. warp0 = exact Viterbi (+parallel bp & backtrack),
//           warp1 = linear-domain Z reduction + gold score.
// ---------------------------------------------------------------------------
__global__ __launch_bounds__(64)
void crf_kernel(const int* __restrict__ asl,
                const float* __restrict__ trans,
                float* __restrict__ out)
{
    __shared__ __align__(16) float sf[NS * TT];      // feats for this batch
    __shared__ __align__(16) float sdelta[NS * TT];  // viterbi deltas
    __shared__ float str[16];

    int b = blockIdx.x;
    int tid = threadIdx.x;
    int lane = tid & 31;
    int w = tid >> 5;

    const float4* gf = reinterpret_cast<const float4*>(g_feats + (size_t)b * NS * TT);
    float4* sf4 = reinterpret_cast<float4*>(sf);
    float4* sd4 = reinterpret_cast<float4*>(sdelta);
    for (int i = tid; i < NS; i += 64) sf4[i] = gf[i];
    if (tid < 16) str[tid] = trans[tid];
    __syncthreads();

    if (w == 0) {
        // ===================== Viterbi =====================
        float tr[16];
        #pragma unroll
        for (int i = 0; i < 16; i++) tr[i] = str[i];

        int lt = 0;
        if (lane == 0) {
            float4 f0 = sf4[0];
            float d0 = f0.x + tr[TSTART * 4 + 0];
            float d1 = f0.y + tr[TSTART * 4 + 1];
            float d2 = f0.z + tr[TSTART * 4 + 2];
            float d3 = f0.w + tr[TSTART * 4 + 3];
            sd4[0] = make_float4(d0, d1, d2, d3);
            #pragma unroll 4
            for (int s = 1; s < NS; s++) {
                float4 f = sf4[s];
                float m0 = fmaxf(fmaxf(d0 + tr[0],  d1 + tr[4]),  fmaxf(d2 + tr[8],  d3 + tr[12]));
                float m1 = fmaxf(fmaxf(d0 + tr[1],  d1 + tr[5]),  fmaxf(d2 + tr[9],  d3 + tr[13]));
                float m2 = fmaxf(fmaxf(d0 + tr[2],  d1 + tr[6]),  fmaxf(d2 + tr[10], d3 + tr[14]));
                float m3 = fmaxf(fmaxf(d0 + tr[3],  d1 + tr[7]),  fmaxf(d2 + tr[11], d3 + tr[15]));
                d0 = m0 + f.x; d1 = m1 + f.y; d2 = m2 + f.z; d3 = m3 + f.w;
                sd4[s] = make_float4(d0, d1, d2, d3);
            }
            float w0 = d0 + tr[0 * 4 + TSTOP];
            float w1 = d1 + tr[1 * 4 + TSTOP];
            float w2 = d2 + tr[2 * 4 + TSTOP];
            float w3 = d3 + tr[3 * 4 + TSTOP];
            float mm = fmaxf(fmaxf(w0, w1), fmaxf(w2, w3));
            lt = (w0 == mm) ? 0 : ((w1 == mm) ? 1 : ((w2 == mm) ? 2 : 3));
        }
        __syncwarp();
        lt = __shfl_sync(0xffffffffu, lt, 0);

        // ---- parallel backpointer recompute: lane l -> steps [16l, 16l+15] ----
        unsigned mp[16];
        mp[0] = 0x03020100u;   // identity (only lane0/k0 keeps it)
        int sbase = lane * 16;
        #pragma unroll
        for (int k = 0; k < 16; k++) {
            int s = sbase + k;
            if (s >= 1) {
                float4 dp = sd4[s - 1];
                unsigned m = 0;
                #pragma unroll
                for (int j = 0; j < 4; j++) {
                    float w0 = dp.x + tr[0 * 4 + j];
                    float w1 = dp.y + tr[1 * 4 + j];
                    float w2 = dp.z + tr[2 * 4 + j];
                    float w3 = dp.w + tr[3 * 4 + j];
                    float mm = fmaxf(fmaxf(w0, w1), fmaxf(w2, w3));
                    unsigned bi = (w0 == mm) ? 0u : ((w1 == mm) ? 1u : ((w2 == mm) ? 2u : 3u));
                    m |= bi << (8 * j);
                }
                mp[k] = m;
            }
        }

        // segment map G_l = mp[0] ∘ mp[1] ∘ ... ∘ mp[15]
        unsigned G = mp[15];
        #pragma unroll
        for (int k = 14; k >= 0; k--) G = cmap(mp[k], G);

        // inclusive suffix scan of G, then shift -> S_l = G_{l+1} ∘ ... ∘ G_31
        unsigned T = G;
        #pragma unroll
        for (int off = 1; off < 32; off <<= 1) {
            unsigned g2 = __shfl_down_sync(0xffffffffu, T, off);
            if (lane + off < 32) T = cmap(T, g2);
        }
        unsigned S = __shfl_down_sync(0xffffffffu, T, 1);
        if (lane == 31) S = 0x03020100u;

        unsigned t = (S >> (8 * (unsigned)lt)) & 3u;
        float* outp = out + OFF_CRF_PRED + b * NS + sbase;
        outp[15] = (float)t;
        #pragma unroll
        for (int k = 15; k >= 1; k--) {
            t = (mp[k] >> (8 * t)) & 3u;
            outp[k - 1] = (float)t;
        }
    } else {
        // ===================== Z (linear domain) + gold =====================
        float tr[16], etr[16];
        #pragma unroll
        for (int i = 0; i < 16; i++) { tr[i] = str[i]; etr[i] = __expf(str[i]); }

        float C[4][4];
        float logacc = 0.f;
        int sbase = lane * 16;
        {
            float4 f = sf4[sbase];
            float e0 = __expf(f.x), e1 = __expf(f.y), e2 = __expf(f.z), e3 = __expf(f.w);
            if (lane == 0) {
                float b0 = __expf(tr[TSTART * 4 + 0]) * e0;
                float b1 = __expf(tr[TSTART * 4 + 1]) * e1;
                float b2 = __expf(tr[TSTART * 4 + 2]) * e2;
                float b3 = __expf(tr[TSTART * 4 + 3]) * e3;
                #pragma unroll
                for (int i = 0; i < 4; i++) { C[i][0] = b0; C[i][1] = b1; C[i][2] = b2; C[i][3] = b3; }
            } else {
                #pragma unroll
                for (int i = 0; i < 4; i++) {
                    C[i][0] = etr[i * 4 + 0] * e0;
                    C[i][1] = etr[i * 4 + 1] * e1;
                    C[i][2] = etr[i * 4 + 2] * e2;
                    C[i][3] = etr[i * 4 + 3] * e3;
                }
            }
        }
        #pragma unroll
        for (int k = 1; k < 16; k++) {
            float4 f = sf4[sbase + k];
            float e0 = __expf(f.x), e1 = __expf(f.y), e2 = __expf(f.z), e3 = __expf(f.w);
            #pragma unroll
            for (int i = 0; i < 4; i++) {
                float t0 = C[i][0] * etr[0] + C[i][1] * etr[4] + C[i][2] * etr[8]  + C[i][3] * etr[12];
                float t1 = C[i][0] * etr[1] + C[i][1] * etr[5] + C[i][2] * etr[9]  + C[i][3] * etr[13];
                float t2 = C[i][0] * etr[2] + C[i][1] * etr[6] + C[i][2] * etr[10] + C[i][3] * etr[14];
                float t3 = C[i][0] * etr[3] + C[i][1] * etr[7] + C[i][2] * etr[11] + C[i][3] * etr[15];
                C[i][0] = t0 * e0; C[i][1] = t1 * e1; C[i][2] = t2 * e2; C[i][3] = t3 * e3;
            }
            if ((k & 7) == 7) rescale16(C, logacc);
        }

        // ordered tree reduction over lanes (left-to-right matrix product)
        #pragma unroll
        for (int off = 1; off < 32; off <<= 1) {
            float R[4][4];
            #pragma unroll
            for (int i = 0; i < 4; i++)
                #pragma unroll
                for (int j = 0; j < 4; j++)
                    R[i][j] = __shfl_down_sync(0xffffffffu, C[i][j], off);
            float lg2 = __shfl_down_sync(0xffffffffu, logacc, off);
            if ((lane & (2 * off - 1)) == 0) {
                float Tm[4][4];
                #pragma unroll
                for (int i = 0; i < 4; i++)
                    #pragma unroll
                    for (int j = 0; j < 4; j++)
                        Tm[i][j] = C[i][0] * R[0][j] + C[i][1] * R[1][j]
                                 + C[i][2] * R[2][j] + C[i][3] * R[3][j];
                #pragma unroll
                for (int i = 0; i < 4; i++)
                    #pragma unroll
                    for (int j = 0; j < 4; j++) C[i][j] = Tm[i][j];
                logacc += lg2;
                rescale16(C, logacc);
            }
        }

        float Z = 0.f;
        if (lane == 0) {
            float z0 = C[0][0] * etr[0 * 4 + TSTOP] + C[0][1] * etr[1 * 4 + TSTOP]
                     + C[0][2] * etr[2 * 4 + TSTOP] + C[0][3] * etr[3 * 4 + TSTOP];
            Z = logacc + __logf(z0);
        }

        // ---- gold score ----
        const int* tagp = asl + b * NS1 + 1;
        float partial = 0.f;
        for (int s = lane; s < NS; s += 32) {
            int tg = tagp[s];
            partial += sf[s * 4 + tg];
            if (s < NS - 1) partial += str[tg * 4 + tagp[s + 1]];
        }
        #pragma unroll
        for (int o = 16; o; o >>= 1) partial += __shfl_xor_sync(0xffffffffu, partial, o);

        if (lane == 0) {
            float gold = partial + str[TSTART * 4 + tagp[0]] + str[tagp[NS - 1] * 4 + TSTOP];
            g_zg[b] = Z - gold;
        }
    }
}

// ---------------------------------------------------------------------------
// Kernel C: final loss reductions
// ---------------------------------------------------------------------------
__global__ __launch_bounds__(32)
void loss_kernel(float* __restrict__ out)
{
    int lane = threadIdx.x;
    float v1 = g_isqa_loss[lane] + g_isqa_loss[lane + 32];
    float v2 = g_zg[lane] + g_zg[lane + 32];
    #pragma unroll
    for (int o = 16; o; o >>= 1) {
        v1 += __shfl_xor_sync(0xffffffffu, v1, o);
        v2 += __shfl_xor_sync(0xffffffffu, v2, o);
    }
    if (lane == 0) {
        out[OFF_ISQA_LOSS] = v1 * (1.0f / NB);
        out[OFF_CRF_LOSS]  = v2 * (1.0f / NB);
    }
}

extern "C" void kernel_launch(void* const* d_in, const int* in_sizes, int n_in,
                              void* d_out, int out_size)
{
    const float* emb   = (const float*)d_in[0];
    const int*   asl   = (const int*)d_in[1];
    const int*   isqa  = (const int*)d_in[2];
    const float* fc2W  = (const float*)d_in[3];
    const float* fc2b  = (const float*)d_in[4];
    const float* crfW  = (const float*)d_in[5];
    const float* crfb  = (const float*)d_in[6];
    const float* trans = (const float*)d_in[7];
    float* out = (float*)d_out;

    int groups = (NB * NS1) / 4;          // 8208 warps of work, 4 rows each
    int blocks = (groups + 7) / 8;        // 8 warps per block -> 1026
    feats_kernel<<<blocks, 256>>>(emb, asl, isqa, fc2W, fc2b, crfW, crfb, out);
    crf_kernel<<<NB, 64>>>(asl, trans, out);
    loss_kernel<<<1, 32>>>(out);
}

// round 3
// speedup vs baseline: 2.7472x; 1.0120x over previous
#include <cuda_runtime.h>

#define HDIM 768
#define TT 4
#define TSTART 2
#define TSTOP 3
#define NB 64
#define NS1 513
#define NS 512

// Output layout (float32), tuple order:
// isqa_pred (64), crf_pred (64*512), isqa_loss (1), crf_loss (1), tags (64*512), IsQA (64)
#define OFF_ISQA_PRED 0
#define OFF_CRF_PRED  64
#define OFF_ISQA_LOSS (64 + NB*NS)          // 32832
#define OFF_CRF_LOSS  (OFF_ISQA_LOSS + 1)   // 32833
#define OFF_TAGS      (OFF_CRF_LOSS + 1)    // 32834
#define OFF_ISQA      (OFF_TAGS + NB*NS)    // 65602

__device__ __align__(16) float g_feats[NB * NS * TT];  // 512 KB scratch
__device__ float g_isqa_loss[NB];
__device__ float g_zg[NB];
__device__ int   g_ctr = 0;

// packed fp32 pair add (two exact IEEE rn adds in one instruction)
__device__ __forceinline__ float2 fadd2(float2 a, float2 b) {
    float2 r;
    asm("add.rn.f32x2 %0, %1, %2;"
        : "=l"(reinterpret_cast<unsigned long long&>(r))
        : "l"(reinterpret_cast<unsigned long long&>(a)),
          "l"(reinterpret_cast<unsigned long long&>(b)));
    return r;
}

// ---------------------------------------------------------------------------
// Kernel A: feats GEMV, thread-owns-column layout.
// grid = 512 blocks x 192 threads; block k handles rows [k*64, k*64+64) of
// the 32768 logical (b,s) rows; weights live entirely in registers.
// ---------------------------------------------------------------------------
__global__ void __launch_bounds__(192, 4)
feats_kernel(const float* __restrict__ emb,
             const int* __restrict__ asl,
             const float* __restrict__ crfW,
             const float* __restrict__ crfb,
             float* __restrict__ out)
{
    __shared__ float sred[2][6][4][4];  // [buf][warp][rowInBatch][tag]
    __shared__ float sbias[4];

    int tid = threadIdx.x;
    int warp = tid >> 5;
    int lane = tid & 31;
    if (tid < 4) sbias[tid] = crfb[tid];

    const float4* W4 = reinterpret_cast<const float4*>(crfW);
    float4 w0 = W4[0 * 192 + tid];
    float4 w1 = W4[1 * 192 + tid];
    float4 w2 = W4[2 * 192 + tid];
    float4 w3 = W4[3 * 192 + tid];

    int rowbase = blockIdx.x * 64;           // logical row = b*512 + s
    int b = rowbase >> 9;
    int s0 = rowbase & 511;

    // tags copy (64 rows, all within batch b)
    if (tid < 64) {
        out[OFF_TAGS + rowbase + tid] = (float)asl[b * NS1 + 1 + s0 + tid];
    }

    const float4* embp = reinterpret_cast<const float4*>(emb)
                       + ((size_t)b * NS1 + 1 + s0) * 192 + tid;

    float4 v0 = embp[0 * 192];
    float4 v1 = embp[1 * 192];
    float4 v2 = embp[2 * 192];
    float4 v3 = embp[3 * 192];
    embp += 4 * 192;

    int mytag = (lane & 1) * 2 + ((lane >> 1) & 1);

    #pragma unroll 2
    for (int batch = 0; batch < 16; batch++) {
        float4 n0 = v0, n1 = v1, n2 = v2, n3 = v3;
        if (batch < 15) {
            n0 = embp[0 * 192];
            n1 = embp[1 * 192];
            n2 = embp[2 * 192];
            n3 = embp[3 * 192];
            embp += 4 * 192;
        }

        float val[4];
        #pragma unroll
        for (int r = 0; r < 4; r++) {
            float4 v = (r == 0) ? v0 : ((r == 1) ? v1 : ((r == 2) ? v2 : v3));
            float p0 = v.x * w0.x + v.y * w0.y + v.z * w0.z + v.w * w0.w;
            float p1 = v.x * w1.x + v.y * w1.y + v.z * w1.z + v.w * w1.w;
            float p2 = v.x * w2.x + v.y * w2.y + v.z * w2.z + v.w * w2.w;
            float p3 = v.x * w3.x + v.y * w3.y + v.z * w3.z + v.w * w3.w;

            // butterfly reduce-scatter: 6 shfl per row
            float s0a = (lane & 1) ? p0 : p2;
            float s1a = (lane & 1) ? p1 : p3;
            float r0 = __shfl_xor_sync(0xffffffffu, s0a, 1);
            float r1 = __shfl_xor_sync(0xffffffffu, s1a, 1);
            float q0, q1;
            if (lane & 1) { q0 = p2 + r0; q1 = p3 + r1; }   // odd keeps tags {2,3}
            else          { q0 = p0 + r0; q1 = p1 + r1; }   // even keeps {0,1}
            float sB = (lane & 2) ? q0 : q1;
            float rB = __shfl_xor_sync(0xffffffffu, sB, 2);
            float vv = ((lane & 2) ? q1 : q0) + rB;
            vv += __shfl_xor_sync(0xffffffffu, vv, 4);
            vv += __shfl_xor_sync(0xffffffffu, vv, 8);
            vv += __shfl_xor_sync(0xffffffffu, vv, 16);
            val[r] = vv;   // all lanes: warp total for tag `mytag`
        }

        int buf = batch & 1;
        if (lane < 4) {
            #pragma unroll
            for (int r = 0; r < 4; r++)
                sred[buf][warp][r][mytag] = val[r];
        }
        __syncthreads();
        if (tid < 16) {
            int r = tid >> 2, t = tid & 3;
            float s = sred[buf][0][r][t] + sred[buf][1][r][t] + sred[buf][2][r][t]
                    + sred[buf][3][r][t] + sred[buf][4][r][t] + sred[buf][5][r][t]
                    + sbias[t];
            g_feats[(size_t)(rowbase + batch * 4 + r) * 4 + t] = s;
        }
        v0 = n0; v1 = n1; v2 = n2; v3 = n3;
    }
}

// tag-map composition: (a ∘ b)(t) = a[b[t]], maps stored as 4 bytes (values 0..3)
__device__ __forceinline__ unsigned cmap(unsigned a, unsigned b) {
    unsigned sel = (b & 3u) | ((b >> 4) & 0x30u) | ((b >> 8) & 0x300u) | ((b >> 12) & 0x3000u);
    return __byte_perm(a, 0, sel);
}

__device__ __forceinline__ void rescale16(float C[4][4], float& logacc) {
    float mx = C[0][0];
    #pragma unroll
    for (int i = 0; i < 4; i++)
        #pragma unroll
        for (int j = 0; j < 4; j++) mx = fmaxf(mx, C[i][j]);
    int e = (__float_as_int(mx) >> 23) & 255;
    float inv = __int_as_float((254 - e) << 23);   // exact 2^(127-e)
    logacc += (float)(e - 127) * 0.6931471805599453f;
    #pragma unroll
    for (int i = 0; i < 4; i++)
        #pragma unroll
        for (int j = 0; j < 4; j++) C[i][j] *= inv;
}

// ---------------------------------------------------------------------------
// Kernel B: per-batch CRF. warp0 = exact Viterbi (packed adds) + parallel bp
//           + backtrack; warp1 = linear-domain Z + gold; warp2 = CLS/isqa.
//           Last block computes the two mean losses.
// ---------------------------------------------------------------------------
__global__ void __launch_bounds__(96)
crf_kernel(const float* __restrict__ emb,
           const int* __restrict__ asl,
           const int* __restrict__ isqa,
           const float* __restrict__ fc2W,
           const float* __restrict__ fc2b,
           const float* __restrict__ trans,
           float* __restrict__ out)
{
    __shared__ __align__(16) float sf[NS * TT];      // feats for this batch (8KB)
    __shared__ __align__(16) float sdelta[NS * TT];  // viterbi deltas (8KB)
    __shared__ float str[16];
    __shared__ int sflag;

    int b = blockIdx.x;
    int tid = threadIdx.x;
    int lane = tid & 31;
    int w = tid >> 5;

    const float4* gf = reinterpret_cast<const float4*>(g_feats + (size_t)b * NS * TT);
    float4* sf4 = reinterpret_cast<float4*>(sf);
    float4* sd4 = reinterpret_cast<float4*>(sdelta);
    for (int i = tid; i < NS; i += 96) sf4[i] = gf[i];
    if (tid < 16) str[tid] = trans[tid];
    if (tid == 0) sflag = 0;
    __syncthreads();

    if (w == 0) {
        // ===================== Viterbi =====================
        float tr[16];
        #pragma unroll
        for (int i = 0; i < 16; i++) tr[i] = str[i];

        int lt = 0;
        if (lane == 0) {
            float2 t01[4], t23[4];
            #pragma unroll
            for (int j = 0; j < 4; j++) {
                t01[j] = make_float2(tr[0 * 4 + j], tr[1 * 4 + j]);
                t23[j] = make_float2(tr[2 * 4 + j], tr[3 * 4 + j]);
            }
            float4 f0 = sf4[0];
            float2 d01 = make_float2(f0.x + tr[TSTART * 4 + 0], f0.y + tr[TSTART * 4 + 1]);
            float2 d23 = make_float2(f0.z + tr[TSTART * 4 + 2], f0.w + tr[TSTART * 4 + 3]);
            sd4[0] = make_float4(d01.x, d01.y, d23.x, d23.y);
            #pragma unroll 4
            for (int s = 1; s < NS; s++) {
                float4 f = sf4[s];
                float2 a0 = fadd2(d01, t01[0]); float2 b0 = fadd2(d23, t23[0]);
                float2 a1 = fadd2(d01, t01[1]); float2 b1 = fadd2(d23, t23[1]);
                float2 a2 = fadd2(d01, t01[2]); float2 b2 = fadd2(d23, t23[2]);
                float2 a3 = fadd2(d01, t01[3]); float2 b3 = fadd2(d23, t23[3]);
                float m0 = fmaxf(fmaxf(a0.x, a0.y), fmaxf(b0.x, b0.y));
                float m1 = fmaxf(fmaxf(a1.x, a1.y), fmaxf(b1.x, b1.y));
                float m2 = fmaxf(fmaxf(a2.x, a2.y), fmaxf(b2.x, b2.y));
                float m3 = fmaxf(fmaxf(a3.x, a3.y), fmaxf(b3.x, b3.y));
                d01 = fadd2(make_float2(m0, m1), make_float2(f.x, f.y));
                d23 = fadd2(make_float2(m2, m3), make_float2(f.z, f.w));
                sd4[s] = make_float4(d01.x, d01.y, d23.x, d23.y);
            }
            float w0v = d01.x + tr[0 * 4 + TSTOP];
            float w1v = d01.y + tr[1 * 4 + TSTOP];
            float w2v = d23.x + tr[2 * 4 + TSTOP];
            float w3v = d23.y + tr[3 * 4 + TSTOP];
            float mm = fmaxf(fmaxf(w0v, w1v), fmaxf(w2v, w3v));
            lt = (w0v == mm) ? 0 : ((w1v == mm) ? 1 : ((w2v == mm) ? 2 : 3));
        }
        __syncwarp();
        lt = __shfl_sync(0xffffffffu, lt, 0);

        // ---- parallel backpointer recompute: lane l -> steps [16l, 16l+15] ----
        unsigned mp[16];
        mp[0] = 0x03020100u;   // identity (only lane0/k0 keeps it)
        int sbase = lane * 16;
        #pragma unroll
        for (int k = 0; k < 16; k++) {
            int s = sbase + k;
            if (s >= 1) {
                float4 dp = sd4[s - 1];
                unsigned m = 0;
                #pragma unroll
                for (int j = 0; j < 4; j++) {
                    float w0v = dp.x + tr[0 * 4 + j];
                    float w1v = dp.y + tr[1 * 4 + j];
                    float w2v = dp.z + tr[2 * 4 + j];
                    float w3v = dp.w + tr[3 * 4 + j];
                    float mm = fmaxf(fmaxf(w0v, w1v), fmaxf(w2v, w3v));
                    unsigned bi = (w0v == mm) ? 0u : ((w1v == mm) ? 1u : ((w2v == mm) ? 2u : 3u));
                    m |= bi << (8 * j);
                }
                mp[k] = m;
            }
        }

        unsigned G = mp[15];
        #pragma unroll
        for (int k = 14; k >= 0; k--) G = cmap(mp[k], G);

        unsigned T = G;
        #pragma unroll
        for (int off = 1; off < 32; off <<= 1) {
            unsigned g2 = __shfl_down_sync(0xffffffffu, T, off);
            if (lane + off < 32) T = cmap(T, g2);
        }
        unsigned S = __shfl_down_sync(0xffffffffu, T, 1);
        if (lane == 31) S = 0x03020100u;

        unsigned t = (S >> (8 * (unsigned)lt)) & 3u;
        float* outp = out + OFF_CRF_PRED + b * NS + sbase;
        outp[15] = (float)t;
        #pragma unroll
        for (int k = 15; k >= 1; k--) {
            t = (mp[k] >> (8 * t)) & 3u;
            outp[k - 1] = (float)t;
        }
    } else if (w == 1) {
        // ===================== Z (linear domain) + gold =====================
        float tr[16], etr[16];
        #pragma unroll
        for (int i = 0; i < 16; i++) { tr[i] = str[i]; etr[i] = __expf(str[i]); }

        float C[4][4];
        float logacc = 0.f;
        int sbase = lane * 16;
        {
            float4 f = sf4[sbase];
            float e0 = __expf(f.x), e1 = __expf(f.y), e2 = __expf(f.z), e3 = __expf(f.w);
            if (lane == 0) {
                float b0 = __expf(tr[TSTART * 4 + 0]) * e0;
                float b1 = __expf(tr[TSTART * 4 + 1]) * e1;
                float b2 = __expf(tr[TSTART * 4 + 2]) * e2;
                float b3 = __expf(tr[TSTART * 4 + 3]) * e3;
                #pragma unroll
                for (int i = 0; i < 4; i++) { C[i][0] = b0; C[i][1] = b1; C[i][2] = b2; C[i][3] = b3; }
            } else {
                #pragma unroll
                for (int i = 0; i < 4; i++) {
                    C[i][0] = etr[i * 4 + 0] * e0;
                    C[i][1] = etr[i * 4 + 1] * e1;
                    C[i][2] = etr[i * 4 + 2] * e2;
                    C[i][3] = etr[i * 4 + 3] * e3;
                }
            }
        }
        #pragma unroll
        for (int k = 1; k < 16; k++) {
            float4 f = sf4[sbase + k];
            float e0 = __expf(f.x), e1 = __expf(f.y), e2 = __expf(f.z), e3 = __expf(f.w);
            #pragma unroll
            for (int i = 0; i < 4; i++) {
                float t0 = C[i][0] * etr[0] + C[i][1] * etr[4] + C[i][2] * etr[8]  + C[i][3] * etr[12];
                float t1 = C[i][0] * etr[1] + C[i][1] * etr[5] + C[i][2] * etr[9]  + C[i][3] * etr[13];
                float t2 = C[i][0] * etr[2] + C[i][1] * etr[6] + C[i][2] * etr[10] + C[i][3] * etr[14];
                float t3 = C[i][0] * etr[3] + C[i][1] * etr[7] + C[i][2] * etr[11] + C[i][3] * etr[15];
                C[i][0] = t0 * e0; C[i][1] = t1 * e1; C[i][2] = t2 * e2; C[i][3] = t3 * e3;
            }
            if ((k & 7) == 7) rescale16(C, logacc);
        }

        #pragma unroll
        for (int off = 1; off < 32; off <<= 1) {
            float R[4][4];
            #pragma unroll
            for (int i = 0; i < 4; i++)
                #pragma unroll
                for (int j = 0; j < 4; j++)
                    R[i][j] = __shfl_down_sync(0xffffffffu, C[i][j], off);
            float lg2 = __shfl_down_sync(0xffffffffu, logacc, off);
            if ((lane & (2 * off - 1)) == 0) {
                float Tm[4][4];
                #pragma unroll
                for (int i = 0; i < 4; i++)
                    #pragma unroll
                    for (int j = 0; j < 4; j++)
                        Tm[i][j] = C[i][0] * R[0][j] + C[i][1] * R[1][j]
                                 + C[i][2] * R[2][j] + C[i][3] * R[3][j];
                #pragma unroll
                for (int i = 0; i < 4; i++)
                    #pragma unroll
                    for (int j = 0; j < 4; j++) C[i][j] = Tm[i][j];
                logacc += lg2;
                rescale16(C, logacc);
            }
        }

        float Z = 0.f;
        if (lane == 0) {
            float z0 = C[0][0] * etr[0 * 4 + TSTOP] + C[0][1] * etr[1 * 4 + TSTOP]
                     + C[0][2] * etr[2 * 4 + TSTOP] + C[0][3] * etr[3 * 4 + TSTOP];
            Z = logacc + __logf(z0);
        }

        // ---- gold score ----
        const int* tagp = asl + b * NS1 + 1;
        float partial = 0.f;
        for (int s = lane; s < NS; s += 32) {
            int tg = tagp[s];
            partial += sf[s * 4 + tg];
            if (s < NS - 1) partial += str[tg * 4 + tagp[s + 1]];
        }
        #pragma unroll
        for (int o = 16; o; o >>= 1) partial += __shfl_xor_sync(0xffffffffu, partial, o);

        if (lane == 0) {
            float gold = partial + str[TSTART * 4 + tagp[0]] + str[tagp[NS - 1] * 4 + TSTOP];
            g_zg[b] = Z - gold;
            __threadfence();
        }
    } else {
        // ===================== CLS / isqa head =====================
        const float4* crow = reinterpret_cast<const float4*>(emb) + (size_t)b * NS1 * 192;
        const float4* f2 = reinterpret_cast<const float4*>(fc2W);
        float a0 = 0.f, a1 = 0.f;
        #pragma unroll
        for (int j = 0; j < 6; j++) {
            int c = lane + 32 * j;
            float4 v = crow[c];
            float4 u0 = f2[c];
            float4 u1 = f2[192 + c];
            a0 += v.x * u0.x + v.y * u0.y + v.z * u0.z + v.w * u0.w;
            a1 += v.x * u1.x + v.y * u1.y + v.z * u1.z + v.w * u1.w;
        }
        #pragma unroll
        for (int o = 16; o; o >>= 1) {
            a0 += __shfl_xor_sync(0xffffffffu, a0, o);
            a1 += __shfl_xor_sync(0xffffffffu, a1, o);
        }
        if (lane == 0) {
            float l0 = a0 + fc2b[0];
            float l1 = a1 + fc2b[1];
            int pred = (l1 > l0) ? 1 : 0;
            float m = fmaxf(l0, l1);
            float lse = m + __logf(__expf(l0 - m) + __expf(l1 - m));
            int q = isqa[b];
            out[OFF_ISQA_PRED + b] = (float)pred;
            out[OFF_ISQA + b] = (float)q;
            g_isqa_loss[b] = lse - (q ? l1 : l0);
            __threadfence();
        }
    }

    // ===================== last block computes losses =====================
    __syncthreads();
    if (tid == 0) {
        int t = atomicAdd(&g_ctr, 1);
        sflag = (t == NB - 1) ? 1 : 0;
    }
    __syncthreads();
    if (sflag) {
        __threadfence();
        if (tid < 32) {
            float v1 = g_isqa_loss[tid] + g_isqa_loss[tid + 32];
            float v2 = g_zg[tid] + g_zg[tid + 32];
            #pragma unroll
            for (int o = 16; o; o >>= 1) {
                v1 += __shfl_xor_sync(0xffffffffu, v1, o);
                v2 += __shfl_xor_sync(0xffffffffu, v2, o);
            }
            if (tid == 0) {
                out[OFF_ISQA_LOSS] = v1 * (1.0f / NB);
                out[OFF_CRF_LOSS]  = v2 * (1.0f / NB);
                g_ctr = 0;  // reset for next graph replay
            }
        }
    }
}

extern "C" void kernel_launch(void* const* d_in, const int* in_sizes, int n_in,
                              void* d_out, int out_size)
{
    const float* emb   = (const float*)d_in[0];
    const int*   asl   = (const int*)d_in[1];
    const int*   isqa  = (const int*)d_in[2];
    const float* fc2W  = (const float*)d_in[3];
    const float* fc2b  = (const float*)d_in[4];
    const float* crfW  = (const float*)d_in[5];
    const float* crfb  = (const float*)d_in[6];
    const float* trans = (const float*)d_in[7];
    float* out = (float*)d_out;

    feats_kernel<<<512, 192>>>(emb, asl, crfW, crfb, out);
    crf_kernel<<<NB, 96>>>(emb, asl, isqa, fc2W, fc2b, trans, out);
}

// round 5
// speedup vs baseline: 2.8435x; 1.0350x over previous
#include <cuda_runtime.h>

#define HDIM 768
#define TT 4
#define TSTART 2
#define TSTOP 3
#define NB 64
#define NS1 513
#define NS 512

// Output layout (float32), tuple order:
// isqa_pred (64), crf_pred (64*512), isqa_loss (1), crf_loss (1), tags (64*512), IsQA (64)
#define OFF_ISQA_PRED 0
#define OFF_CRF_PRED  64
#define OFF_ISQA_LOSS (64 + NB*NS)          // 32832
#define OFF_CRF_LOSS  (OFF_ISQA_LOSS + 1)   // 32833
#define OFF_TAGS      (OFF_CRF_LOSS + 1)    // 32834
#define OFF_ISQA      (OFF_TAGS + NB*NS)    // 65602

__device__ __align__(16) float g_feats[NB * NS * TT];  // 512 KB scratch
__device__ float g_isqa_loss[NB];
__device__ float g_zg[NB];
__device__ int   g_ctr = 0;

// exact a+b issued as FFMA-imm (rt_SMSP=1 on the fma pipe vs 2 for FADD):
// a*1.0f + b, single rounding -> bit-identical to FADD.
__device__ __forceinline__ float addx(float a, float b) {
    float r;
    asm("fma.rn.f32 %0, %1, 0f3F800000, %2;" : "=f"(r) : "f"(a), "f"(b));
    return r;
}

// ---------------------------------------------------------------------------
// Kernel A: feats GEMV, thread-owns-column layout.
// grid = 1024 blocks x 192 threads; block k handles rows [k*32, k*32+32) of
// the 32768 logical (b,s) rows; weights live entirely in registers.
// ---------------------------------------------------------------------------
__global__ void __launch_bounds__(192, 4)
feats_kernel(const float* __restrict__ emb,
             const int* __restrict__ asl,
             const float* __restrict__ crfW,
             const float* __restrict__ crfb,
             float* __restrict__ out)
{
    __shared__ float sred[2][6][4][4];  // [buf][warp][rowInBatch][tag]
    __shared__ float sbias[4];

    int tid = threadIdx.x;
    int warp = tid >> 5;
    int lane = tid & 31;
    if (tid < 4) sbias[tid] = crfb[tid];

    const float4* W4 = reinterpret_cast<const float4*>(crfW);
    float4 w0 = W4[0 * 192 + tid];
    float4 w1 = W4[1 * 192 + tid];
    float4 w2 = W4[2 * 192 + tid];
    float4 w3 = W4[3 * 192 + tid];

    int rowbase = blockIdx.x * 32;           // logical row = b*512 + s
    int b = rowbase >> 9;
    int s0 = rowbase & 511;

    // tags copy (32 rows, all within batch b)
    if (tid < 32) {
        out[OFF_TAGS + rowbase + tid] = (float)asl[b * NS1 + 1 + s0 + tid];
    }

    const float4* embp = reinterpret_cast<const float4*>(emb)
                       + ((size_t)b * NS1 + 1 + s0) * 192 + tid;

    float4 v0 = embp[0 * 192];
    float4 v1 = embp[1 * 192];
    float4 v2 = embp[2 * 192];
    float4 v3 = embp[3 * 192];
    embp += 4 * 192;

    int mytag = (lane & 1) * 2 + ((lane >> 1) & 1);

    #pragma unroll 2
    for (int batch = 0; batch < 8; batch++) {
        float4 n0 = v0, n1 = v1, n2 = v2, n3 = v3;
        if (batch < 7) {
            n0 = embp[0 * 192];
            n1 = embp[1 * 192];
            n2 = embp[2 * 192];
            n3 = embp[3 * 192];
            embp += 4 * 192;
        }

        float val[4];
        #pragma unroll
        for (int r = 0; r < 4; r++) {
            float4 v = (r == 0) ? v0 : ((r == 1) ? v1 : ((r == 2) ? v2 : v3));
            float p0 = v.x * w0.x + v.y * w0.y + v.z * w0.z + v.w * w0.w;
            float p1 = v.x * w1.x + v.y * w1.y + v.z * w1.z + v.w * w1.w;
            float p2 = v.x * w2.x + v.y * w2.y + v.z * w2.z + v.w * w2.w;
            float p3 = v.x * w3.x + v.y * w3.y + v.z * w3.z + v.w * w3.w;

            // butterfly reduce-scatter: 6 shfl per row
            float s0a = (lane & 1) ? p0 : p2;
            float s1a = (lane & 1) ? p1 : p3;
            float r0 = __shfl_xor_sync(0xffffffffu, s0a, 1);
            float r1 = __shfl_xor_sync(0xffffffffu, s1a, 1);
            float q0, q1;
            if (lane & 1) { q0 = p2 + r0; q1 = p3 + r1; }   // odd keeps tags {2,3}
            else          { q0 = p0 + r0; q1 = p1 + r1; }   // even keeps {0,1}
            float sB = (lane & 2) ? q0 : q1;
            float rB = __shfl_xor_sync(0xffffffffu, sB, 2);
            float vv = ((lane & 2) ? q1 : q0) + rB;
            vv += __shfl_xor_sync(0xffffffffu, vv, 4);
            vv += __shfl_xor_sync(0xffffffffu, vv, 8);
            vv += __shfl_xor_sync(0xffffffffu, vv, 16);
            val[r] = vv;   // all lanes: warp total for tag `mytag`
        }

        int buf = batch & 1;
        if (lane < 4) {
            #pragma unroll
            for (int r = 0; r < 4; r++)
                sred[buf][warp][r][mytag] = val[r];
        }
        __syncthreads();
        if (tid < 16) {
            int r = tid >> 2, t = tid & 3;
            float s = sred[buf][0][r][t] + sred[buf][1][r][t] + sred[buf][2][r][t]
                    + sred[buf][3][r][t] + sred[buf][4][r][t] + sred[buf][5][r][t]
                    + sbias[t];
            g_feats[(size_t)(rowbase + batch * 4 + r) * 4 + t] = s;
        }
        v0 = n0; v1 = n1; v2 = n2; v3 = n3;
    }
}

// tag-map composition: (a ∘ b)(t) = a[b[t]], maps stored as 4 bytes (values 0..3)
__device__ __forceinline__ unsigned cmap(unsigned a, unsigned b) {
    unsigned sel = (b & 3u) | ((b >> 4) & 0x30u) | ((b >> 8) & 0x300u) | ((b >> 12) & 0x3000u);
    return __byte_perm(a, 0, sel);
}

__device__ __forceinline__ void rescale16(float C[4][4], float& logacc) {
    float mx = C[0][0];
    #pragma unroll
    for (int i = 0; i < 4; i++)
        #pragma unroll
        for (int j = 0; j < 4; j++) mx = fmaxf(mx, C[i][j]);
    int e = (__float_as_int(mx) >> 23) & 255;
    float inv = __int_as_float((254 - e) << 23);   // exact 2^(127-e)
    logacc += (float)(e - 127) * 0.6931471805599453f;
    #pragma unroll
    for (int i = 0; i < 4; i++)
        #pragma unroll
        for (int j = 0; j < 4; j++) C[i][j] *= inv;
}

// ---------------------------------------------------------------------------
// Kernel B: per-batch CRF. warp0 = exact Viterbi (FFMA-imm adds) + parallel bp
//           + backtrack; warp1 = linear-domain Z + gold; warp2 = CLS/isqa.
//           Last block computes the two mean losses.
// ---------------------------------------------------------------------------
__global__ void __launch_bounds__(96)
crf_kernel(const float* __restrict__ emb,
           const int* __restrict__ asl,
           const int* __restrict__ isqa,
           const float* __restrict__ fc2W,
           const float* __restrict__ fc2b,
           const float* __restrict__ trans,
           float* __restrict__ out)
{
    __shared__ __align__(16) float sf[NS * TT];      // feats for this batch (8KB)
    __shared__ __align__(16) float sdelta[NS * TT];  // viterbi deltas (8KB)
    __shared__ float str[16];
    __shared__ int sflag;

    int b = blockIdx.x;
    int tid = threadIdx.x;
    int lane = tid & 31;
    int w = tid >> 5;

    const float4* gf = reinterpret_cast<const float4*>(g_feats + (size_t)b * NS * TT);
    float4* sf4 = reinterpret_cast<float4*>(sf);
    float4* sd4 = reinterpret_cast<float4*>(sdelta);
    for (int i = tid; i < NS; i += 96) sf4[i] = gf[i];
    if (tid < 16) str[tid] = trans[tid];
    if (tid == 0) sflag = 0;
    __syncthreads();

    if (w == 0) {
        // ===================== Viterbi =====================
        float tr[16];
        #pragma unroll
        for (int i = 0; i < 16; i++) tr[i] = str[i];

        int lt = 0;
        if (lane == 0) {
            float4 f0 = sf4[0];
            float d0 = f0.x + tr[TSTART * 4 + 0];
            float d1 = f0.y + tr[TSTART * 4 + 1];
            float d2 = f0.z + tr[TSTART * 4 + 2];
            float d3 = f0.w + tr[TSTART * 4 + 3];
            sd4[0] = make_float4(d0, d1, d2, d3);
            #pragma unroll 4
            for (int s = 1; s < NS; s++) {
                float4 f = sf4[s];
                float a00 = addx(d0, tr[0]),  a10 = addx(d1, tr[4]),  a20 = addx(d2, tr[8]),  a30 = addx(d3, tr[12]);
                float a01 = addx(d0, tr[1]),  a11 = addx(d1, tr[5]),  a21 = addx(d2, tr[9]),  a31 = addx(d3, tr[13]);
                float a02 = addx(d0, tr[2]),  a12 = addx(d1, tr[6]),  a22 = addx(d2, tr[10]), a32 = addx(d3, tr[14]);
                float a03 = addx(d0, tr[3]),  a13 = addx(d1, tr[7]),  a23 = addx(d2, tr[11]), a33 = addx(d3, tr[15]);
                float m0 = fmaxf(fmaxf(a00, a10), fmaxf(a20, a30));
                float m1 = fmaxf(fmaxf(a01, a11), fmaxf(a21, a31));
                float m2 = fmaxf(fmaxf(a02, a12), fmaxf(a22, a32));
                float m3 = fmaxf(fmaxf(a03, a13), fmaxf(a23, a33));
                d0 = addx(m0, f.x);
                d1 = addx(m1, f.y);
                d2 = addx(m2, f.z);
                d3 = addx(m3, f.w);
                sd4[s] = make_float4(d0, d1, d2, d3);
            }
            float w0v = d0 + tr[0 * 4 + TSTOP];
            float w1v = d1 + tr[1 * 4 + TSTOP];
            float w2v = d2 + tr[2 * 4 + TSTOP];
            float w3v = d3 + tr[3 * 4 + TSTOP];
            float mm = fmaxf(fmaxf(w0v, w1v), fmaxf(w2v, w3v));
            lt = (w0v == mm) ? 0 : ((w1v == mm) ? 1 : ((w2v == mm) ? 2 : 3));
        }
        __syncwarp();
        lt = __shfl_sync(0xffffffffu, lt, 0);

        // ---- parallel backpointer recompute: lane l -> steps [16l, 16l+15] ----
        unsigned mp[16];
        mp[0] = 0x03020100u;   // identity (only lane0/k0 keeps it)
        int sbase = lane * 16;
        #pragma unroll
        for (int k = 0; k < 16; k++) {
            int s = sbase + k;
            if (s >= 1) {
                float4 dp = sd4[s - 1];
                unsigned m = 0;
                #pragma unroll
                for (int j = 0; j < 4; j++) {
                    float w0v = dp.x + tr[0 * 4 + j];
                    float w1v = dp.y + tr[1 * 4 + j];
                    float w2v = dp.z + tr[2 * 4 + j];
                    float w3v = dp.w + tr[3 * 4 + j];
                    float mm = fmaxf(fmaxf(w0v, w1v), fmaxf(w2v, w3v));
                    unsigned bi = (w0v == mm) ? 0u : ((w1v == mm) ? 1u : ((w2v == mm) ? 2u : 3u));
                    m |= bi << (8 * j);
                }
                mp[k] = m;
            }
        }

        unsigned G = mp[15];
        #pragma unroll
        for (int k = 14; k >= 0; k--) G = cmap(mp[k], G);

        unsigned T = G;
        #pragma unroll
        for (int off = 1; off < 32; off <<= 1) {
            unsigned g2 = __shfl_down_sync(0xffffffffu, T, off);
            if (lane + off < 32) T = cmap(T, g2);
        }
        unsigned S = __shfl_down_sync(0xffffffffu, T, 1);
        if (lane == 31) S = 0x03020100u;

        unsigned t = (S >> (8 * (unsigned)lt)) & 3u;
        float* outp = out + OFF_CRF_PRED + b * NS + sbase;
        outp[15] = (float)t;
        #pragma unroll
        for (int k = 15; k >= 1; k--) {
            t = (mp[k] >> (8 * t)) & 3u;
            outp[k - 1] = (float)t;
        }
    } else if (w == 1) {
        // ===================== Z (linear domain) + gold =====================
        float tr[16], etr[16];
        #pragma unroll
        for (int i = 0; i < 16; i++) { tr[i] = str[i]; etr[i] = __expf(str[i]); }

        float C[4][4];
        float logacc = 0.f;
        int sbase = lane * 16;
        {
            float4 f = sf4[sbase];
            float e0 = __expf(f.x), e1 = __expf(f.y), e2 = __expf(f.z), e3 = __expf(f.w);
            if (lane == 0) {
                float b0 = __expf(tr[TSTART * 4 + 0]) * e0;
                float b1 = __expf(tr[TSTART * 4 + 1]) * e1;
                float b2 = __expf(tr[TSTART * 4 + 2]) * e2;
                float b3 = __expf(tr[TSTART * 4 + 3]) * e3;
                #pragma unroll
                for (int i = 0; i < 4; i++) { C[i][0] = b0; C[i][1] = b1; C[i][2] = b2; C[i][3] = b3; }
            } else {
                #pragma unroll
                for (int i = 0; i < 4; i++) {
                    C[i][0] = etr[i * 4 + 0] * e0;
                    C[i][1] = etr[i * 4 + 1] * e1;
                    C[i][2] = etr[i * 4 + 2] * e2;
                    C[i][3] = etr[i * 4 + 3] * e3;
                }
            }
        }
        #pragma unroll
        for (int k = 1; k < 16; k++) {
            float4 f = sf4[sbase + k];
            float e0 = __expf(f.x), e1 = __expf(f.y), e2 = __expf(f.z), e3 = __expf(f.w);
            #pragma unroll
            for (int i = 0; i < 4; i++) {
                float t0 = C[i][0] * etr[0] + C[i][1] * etr[4] + C[i][2] * etr[8]  + C[i][3] * etr[12];
                float t1 = C[i][0] * etr[1] + C[i][1] * etr[5] + C[i][2] * etr[9]  + C[i][3] * etr[13];
                float t2 = C[i][0] * etr[2] + C[i][1] * etr[6] + C[i][2] * etr[10] + C[i][3] * etr[14];
                float t3 = C[i][0] * etr[3] + C[i][1] * etr[7] + C[i][2] * etr[11] + C[i][3] * etr[15];
                C[i][0] = t0 * e0; C[i][1] = t1 * e1; C[i][2] = t2 * e2; C[i][3] = t3 * e3;
            }
            if ((k & 7) == 7) rescale16(C, logacc);
        }

        #pragma unroll
        for (int off = 1; off < 32; off <<= 1) {
            float R[4][4];
            #pragma unroll
            for (int i = 0; i < 4; i++)
                #pragma unroll
                for (int j = 0; j < 4; j++)
                    R[i][j] = __shfl_down_sync(0xffffffffu, C[i][j], off);
            float lg2 = __shfl_down_sync(0xffffffffu, logacc, off);
            if ((lane & (2 * off - 1)) == 0) {
                float Tm[4][4];
                #pragma unroll
                for (int i = 0; i < 4; i++)
                    #pragma unroll
                    for (int j = 0; j < 4; j++)
                        Tm[i][j] = C[i][0] * R[0][j] + C[i][1] * R[1][j]
                                 + C[i][2] * R[2][j] + C[i][3] * R[3][j];
                #pragma unroll
                for (int i = 0; i < 4; i++)
                    #pragma unroll
                    for (int j = 0; j < 4; j++) C[i][j] = Tm[i][j];
                logacc += lg2;
                rescale16(C, logacc);
            }
        }

        float Z = 0.f;
        if (lane == 0) {
            float z0 = C[0][0] * etr[0 * 4 + TSTOP] + C[0][1] * etr[1 * 4 + TSTOP]
                     + C[0][2] * etr[2 * 4 + TSTOP] + C[0][3] * etr[3 * 4 + TSTOP];
            Z = logacc + __logf(z0);
        }

        // ---- gold score ----
        const int* tagp = asl + b * NS1 + 1;
        float partial = 0.f;
        for (int s = lane; s < NS; s += 32) {
            int tg = tagp[s];
            partial += sf[s * 4 + tg];
            if (s < NS - 1) partial += str[tg * 4 + tagp[s + 1]];
        }
        #pragma unroll
        for (int o = 16; o; o >>= 1) partial += __shfl_xor_sync(0xffffffffu, partial, o);

        if (lane == 0) {
            float gold = partial + str[TSTART * 4 + tagp[0]] + str[tagp[NS - 1] * 4 + TSTOP];
            g_zg[b] = Z - gold;
            __threadfence();
        }
    } else {
        // ===================== CLS / isqa head =====================
        const float4* crow = reinterpret_cast<const float4*>(emb) + (size_t)b * NS1 * 192;
        const float4* f2 = reinterpret_cast<const float4*>(fc2W);
        float a0 = 0.f, a1 = 0.f;
        #pragma unroll
        for (int j = 0; j < 6; j++) {
            int c = lane + 32 * j;
            float4 v = crow[c];
            float4 u0 = f2[c];
            float4 u1 = f2[192 + c];
            a0 += v.x * u0.x + v.y * u0.y + v.z * u0.z + v.w * u0.w;
            a1 += v.x * u1.x + v.y * u1.y + v.z * u1.z + v.w * u1.w;
        }
        #pragma unroll
        for (int o = 16; o; o >>= 1) {
            a0 += __shfl_xor_sync(0xffffffffu, a0, o);
            a1 += __shfl_xor_sync(0xffffffffu, a1, o);
        }
        if (lane == 0) {
            float l0 = a0 + fc2b[0];
            float l1 = a1 + fc2b[1];
            int pred = (l1 > l0) ? 1 : 0;
            float m = fmaxf(l0, l1);
            float lse = m + __logf(__expf(l0 - m) + __expf(l1 - m));
            int q = isqa[b];
            out[OFF_ISQA_PRED + b] = (float)pred;
            out[OFF_ISQA + b] = (float)q;
            g_isqa_loss[b] = lse - (q ? l1 : l0);
            __threadfence();
        }
    }

    // ===================== last block computes losses =====================
    __syncthreads();
    if (tid == 0) {
        int t = atomicAdd(&g_ctr, 1);
        sflag = (t == NB - 1) ? 1 : 0;
    }
    __syncthreads();
    if (sflag) {
        __threadfence();
        if (tid < 32) {
            float v1 = g_isqa_loss[tid] + g_isqa_loss[tid + 32];
            float v2 = g_zg[tid] + g_zg[tid + 32];
            #pragma unroll
            for (int o = 16; o; o >>= 1) {
                v1 += __shfl_xor_sync(0xffffffffu, v1, o);
                v2 += __shfl_xor_sync(0xffffffffu, v2, o);
            }
            if (tid == 0) {
                out[OFF_ISQA_LOSS] = v1 * (1.0f / NB);
                out[OFF_CRF_LOSS]  = v2 * (1.0f / NB);
                g_ctr = 0;  // reset for next graph replay
            }
        }
    }
}

extern "C" void kernel_launch(void* const* d_in, const int* in_sizes, int n_in,
                              void* d_out, int out_size)
{
    const float* emb   = (const float*)d_in[0];
    const int*   asl   = (const int*)d_in[1];
    const int*   isqa  = (const int*)d_in[2];
    const float* fc2W  = (const float*)d_in[3];
    const float* fc2b  = (const float*)d_in[4];
    const float* crfW  = (const float*)d_in[5];
    const float* crfb  = (const float*)d_in[6];
    const float* trans = (const float*)d_in[7];
    float* out = (float*)d_out;

    feats_kernel<<<1024, 192>>>(emb, asl, crfW, crfb, out);
    crf_kernel<<<NB, 96>>>(emb, asl, isqa, fc2W, fc2b, trans, out);
}